// round 4
// baseline (speedup 1.0000x reference)
#include <cuda_runtime.h>
#include <cuda_bf16.h>
#include <cstddef>

// Problem constants
#define NN 10000
#define EE 40000
#define DIN 11
#define DD 64
#define FEA 4
#define LL 4
#define BB 512
#define MM 3
#define DH 128          // 2*D, edge-MLP hidden
#define DSQ 4096        // D*D

// ---------------- device scratch (static globals; no allocation) ----------------
__device__ float g_EW[(size_t)EE * DSQ];     // 655 MB: per-edge weight matrices
__device__ float g_hid[(size_t)EE * DH];     // 20 MB: silu(ea@Wn1+bn1)
__device__ float g_h[NN * DD];               // node features
__device__ float g_aggr[NN * DD];            // scatter accumulator
__device__ float g_escore[NN];               // attention logits
__device__ float g_qstar[BB * 2 * DD];
__device__ float g_hs[BB * DD];
__device__ float g_cs[BB * DD];
__device__ int   g_segstart[BB + 1];

__device__ __forceinline__ float sigf(float x) { return 1.f / (1.f + expf(-x)); }

// ---------------- init: zero state ----------------
__global__ void init_state_kernel() {
    int i = blockIdx.x * 256 + threadIdx.x;            // grid covers N*D = 640000
    if (i < NN * DD) g_aggr[i] = 0.f;
    if (i < BB * 2 * DD) g_qstar[i] = 0.f;
    if (i < BB * DD) { g_hs[i] = 0.f; g_cs[i] = 0.f; }
}

// ---------------- segment starts from sorted batch ----------------
__global__ void seg_kernel(const int* __restrict__ batch) {
    int i = blockIdx.x * 256 + threadIdx.x;
    if (i >= NN) return;
    int bcur = batch[i];
    int bprev = (i == 0) ? -1 : batch[i - 1];
    for (int g = bprev + 1; g <= bcur; ++g) g_segstart[g] = i;
    if (i == NN - 1)
        for (int g = bcur + 1; g <= BB; ++g) g_segstart[g] = NN;
}

// ---------------- h0 = x @ W0 + b0 ----------------
__global__ void h0_kernel(const float* __restrict__ x, const float* __restrict__ W0,
                          const float* __restrict__ b0) {
    int idx = blockIdx.x * 256 + threadIdx.x;          // N*D threads
    if (idx >= NN * DD) return;
    int n = idx >> 6, f = idx & 63;
    float acc = b0[f];
#pragma unroll
    for (int d = 0; d < DIN; ++d) acc += x[n * DIN + d] * W0[d * DD + f];
    g_h[idx] = acc;
}

// ---------------- hid = silu(edge_attr @ Wn1 + bn1) ----------------
__global__ void hid_kernel(const float* __restrict__ ea, const float* __restrict__ Wn1,
                           const float* __restrict__ bn1) {
    int e = blockIdx.x;
    int k = threadIdx.x;                               // 128
    float a0 = ea[e * 4 + 0], a1 = ea[e * 4 + 1], a2 = ea[e * 4 + 2], a3 = ea[e * 4 + 3];
    float v = bn1[k] + a0 * Wn1[k] + a1 * Wn1[DH + k] + a2 * Wn1[2 * DH + k] + a3 * Wn1[3 * DH + k];
    g_hid[(size_t)e * DH + k] = v * sigf(v);
}

// ---------------- EW = hid @ Wn2 + bn2  (21.5 GMAC, f32x2 FFMA2 path) ----------------
// Tile: BM=128 (edges) x BN=128 (cols) x BK=32, 256 threads, 8x8 microtile.
__global__ void __launch_bounds__(256) ew_gemm_kernel(const float* __restrict__ Wn2,
                                                      const float* __restrict__ bn2) {
    __shared__ float As[32][128];   // [k][m] transposed
    __shared__ float Bs[32][128];   // [k][n]
    const int tid = threadIdx.x;
    const int tx = tid & 15;        // 16 col groups
    const int ty = tid >> 4;        // 16 row groups
    const int n0 = blockIdx.x * 128;
    const int row0 = blockIdx.y * 128;

    unsigned long long c2[8][4];    // 8 rows x 8 cols packed as f32x2 pairs
#pragma unroll
    for (int i = 0; i < 8; i++)
#pragma unroll
        for (int j = 0; j < 4; j++) c2[i][j] = 0ULL;

    for (int k0 = 0; k0 < DH; k0 += 32) {
        // load A tile (hid rows, 32 k) transposed
#pragma unroll
        for (int r = 0; r < 4; ++r) {
            int idx = tid + r * 256;                   // 1024 float4s
            int m = idx >> 3;
            int k4 = idx & 7;
            float4 v = make_float4(0.f, 0.f, 0.f, 0.f);
            if (row0 + m < EE)
                v = *(const float4*)&g_hid[(size_t)(row0 + m) * DH + k0 + k4 * 4];
            As[k4 * 4 + 0][m] = v.x;
            As[k4 * 4 + 1][m] = v.y;
            As[k4 * 4 + 2][m] = v.z;
            As[k4 * 4 + 3][m] = v.w;
        }
        // load B tile (Wn2 32 k-rows x 128 cols)
#pragma unroll
        for (int r = 0; r < 4; ++r) {
            int idx = tid + r * 256;
            int kk = idx >> 5;
            int n4 = idx & 31;
            *(float4*)&Bs[kk][n4 * 4] =
                *(const float4*)&Wn2[(size_t)(k0 + kk) * DSQ + n0 + n4 * 4];
        }
        __syncthreads();
#pragma unroll
        for (int kk = 0; kk < 32; ++kk) {
            float4 a0 = *(const float4*)&As[kk][ty * 4];
            float4 a1 = *(const float4*)&As[kk][64 + ty * 4];
            ulonglong2 bb0 = *(const ulonglong2*)&Bs[kk][tx * 4];
            ulonglong2 bb1 = *(const ulonglong2*)&Bs[kk][64 + tx * 4];
            unsigned long long b2[4] = {bb0.x, bb0.y, bb1.x, bb1.y};
            float av[8] = {a0.x, a0.y, a0.z, a0.w, a1.x, a1.y, a1.z, a1.w};
            unsigned long long a2[8];
#pragma unroll
            for (int i = 0; i < 8; i++)
                asm("mov.b64 %0, {%1, %1};" : "=l"(a2[i]) : "f"(av[i]));
#pragma unroll
            for (int i = 0; i < 8; i++)
#pragma unroll
                for (int j = 0; j < 4; j++)
                    asm("fma.rn.f32x2 %0, %1, %2, %0;"
                        : "+l"(c2[i][j]) : "l"(a2[i]), "l"(b2[j]));
        }
        __syncthreads();
    }
    // epilogue: unpack, add bias, store
    float4 bv0 = *(const float4*)&bn2[n0 + tx * 4];
    float4 bv1 = *(const float4*)&bn2[n0 + 64 + tx * 4];
#pragma unroll
    for (int i = 0; i < 8; i++) {
        int row = row0 + ((i < 4) ? (ty * 4 + i) : (64 + ty * 4 + (i - 4)));
        if (row >= EE) continue;
        float o[8];
#pragma unroll
        for (int j = 0; j < 4; j++) {
            o[j * 2]     = __uint_as_float((unsigned)(c2[i][j] & 0xffffffffULL));
            o[j * 2 + 1] = __uint_as_float((unsigned)(c2[i][j] >> 32));
        }
        float4 w0 = make_float4(o[0] + bv0.x, o[1] + bv0.y, o[2] + bv0.z, o[3] + bv0.w);
        float4 w1 = make_float4(o[4] + bv1.x, o[5] + bv1.y, o[6] + bv1.z, o[7] + bv1.w);
        *(float4*)&g_EW[(size_t)row * DSQ + n0 + tx * 4] = w0;
        *(float4*)&g_EW[(size_t)row * DSQ + n0 + 64 + tx * 4] = w1;
    }
}

// ---------------- per-layer: msg = h[src] @ EW[e], scatter-add into aggr ----------------
__global__ void conv_msg_kernel(const int* __restrict__ ei) {
    __shared__ float sh[4][64];
    int sub = threadIdx.x >> 6;
    int f = threadIdx.x & 63;
    int e = blockIdx.x * 4 + sub;
    if (e < EE) {
        int src = ei[e];
        sh[sub][f] = g_h[src * DD + f];
    }
    __syncthreads();
    if (e < EE) {
        int dst = ei[EE + e];
        const float* ew = g_EW + (size_t)e * DSQ + f;
        float acc = 0.f;
#pragma unroll
        for (int d = 0; d < 64; ++d) acc += sh[sub][d] * ew[d * 64];
        atomicAdd(&g_aggr[dst * DD + f], acc);
    }
}

// ---------------- per-layer: h += aggr + h@root[l] + bias[l]; re-zero aggr ----------------
__global__ void h_update_kernel(const float* __restrict__ root_l,
                                const float* __restrict__ bias_l) {
    __shared__ float sh[4][64];
    int sub = threadIdx.x >> 6;
    int f = threadIdx.x & 63;
    int n = blockIdx.x * 4 + sub;
    sh[sub][f] = g_h[n * DD + f];
    __syncthreads();
    float acc = 0.f;
#pragma unroll 16
    for (int d = 0; d < 64; ++d) acc += sh[sub][d] * root_l[d * DD + f];
    g_h[n * DD + f] = sh[sub][f] + g_aggr[n * DD + f] + acc + bias_l[f];
    g_aggr[n * DD + f] = 0.f;
}

// ---------------- Set2Set LSTM step ----------------
__global__ void lstm_kernel(const float* __restrict__ Wih, const float* __restrict__ Whh,
                            const float* __restrict__ bvec) {
    int b = blockIdx.x, t = threadIdx.x;
    int warp = t >> 5, lane = t & 31;
    __shared__ float sq[128], shh[64], gs[256];
    if (t < 128) sq[t] = g_qstar[b * 128 + t];
    if (t < 64) shh[t] = g_hs[b * 64 + t];
    __syncthreads();
    for (int g = warp; g < 256; g += 8) {
        float acc = 0.f;
#pragma unroll
        for (int k = 0; k < 4; ++k) acc += sq[lane + k * 32] * Wih[g * 128 + lane + k * 32];
#pragma unroll
        for (int k = 0; k < 2; ++k) acc += shh[lane + k * 32] * Whh[g * 64 + lane + k * 32];
#pragma unroll
        for (int o = 16; o > 0; o >>= 1) acc += __shfl_down_sync(0xffffffffu, acc, o);
        if (lane == 0) gs[g] = acc + bvec[g];
    }
    __syncthreads();
    if (t < 64) {
        float gi = gs[t], gf = gs[64 + t], gg = gs[128 + t], go = gs[192 + t];
        float c = sigf(gf) * g_cs[b * 64 + t] + sigf(gi) * tanhf(gg);
        float hv = sigf(go) * tanhf(c);
        g_cs[b * 64 + t] = c;
        g_hs[b * 64 + t] = hv;
    }
}

// ---------------- e[n] = h[n] . q[batch[n]] ----------------
__global__ void escore_kernel(const int* __restrict__ batch) {
    int warp = threadIdx.x >> 5, lane = threadIdx.x & 31;
    int n = blockIdx.x * 8 + warp;
    if (n >= NN) return;
    int b = batch[n];
    float acc = g_h[n * 64 + lane] * g_hs[b * 64 + lane] +
                g_h[n * 64 + 32 + lane] * g_hs[b * 64 + 32 + lane];
#pragma unroll
    for (int o = 16; o > 0; o >>= 1) acc += __shfl_down_sync(0xffffffffu, acc, o);
    if (lane == 0) g_escore[n] = acc;
}

// ---------------- per-graph softmax pooling; q_star = [q, r] ----------------
__global__ void pool_kernel() {
    int b = blockIdx.x, t = threadIdx.x;               // 64 threads
    int s = g_segstart[b], e = g_segstart[b + 1];
    __shared__ float red[64];
    float m = -3.4e38f;
    for (int n = s + t; n < e; n += 64) m = fmaxf(m, g_escore[n]);
    red[t] = m;
    __syncthreads();
    for (int o = 32; o > 0; o >>= 1) { if (t < o) red[t] = fmaxf(red[t], red[t + o]); __syncthreads(); }
    float mx = red[0];
    __syncthreads();
    float den = 0.f;
    for (int n = s + t; n < e; n += 64) den += expf(g_escore[n] - mx);
    red[t] = den;
    __syncthreads();
    for (int o = 32; o > 0; o >>= 1) { if (t < o) red[t] += red[t + o]; __syncthreads(); }
    float inv = (e > s) ? (1.f / red[0]) : 0.f;
    float rf = 0.f;
    for (int n = s; n < e; ++n) rf += expf(g_escore[n] - mx) * g_h[n * 64 + t];
    rf *= inv;
    g_qstar[b * 128 + t] = g_hs[b * 64 + t];
    g_qstar[b * 128 + 64 + t] = rf;
}

// ---------------- out = silu(q_star @ Wo1 + bo1) @ Wo2 + bo2 ----------------
__global__ void out_kernel(const float* __restrict__ Wo1, const float* __restrict__ bo1,
                           const float* __restrict__ Wo2, const float* __restrict__ bo2,
                           float* __restrict__ out) {
    int b = blockIdx.x, f = threadIdx.x;               // 64 threads
    __shared__ float sq[128];
    __shared__ float red[64];
    sq[f] = g_qstar[b * 128 + f];
    sq[64 + f] = g_qstar[b * 128 + 64 + f];
    __syncthreads();
    float acc = bo1[f];
#pragma unroll 16
    for (int k = 0; k < 128; ++k) acc += sq[k] * Wo1[k * 64 + f];
    float s = acc * sigf(acc);
    red[f] = s * Wo2[f];
    __syncthreads();
    for (int o = 32; o > 0; o >>= 1) { if (f < o) red[f] += red[f + o]; __syncthreads(); }
    if (f == 0) out[b] = red[0] + bo2[0];
}

// ---------------- launch ----------------
extern "C" void kernel_launch(void* const* d_in, const int* in_sizes, int n_in,
                              void* d_out, int out_size) {
    const float* x         = (const float*)d_in[0];
    const int*   edgeidx   = (const int*)d_in[1];
    const float* edge_attr = (const float*)d_in[2];
    const int*   batch     = (const int*)d_in[3];
    const float* W0        = (const float*)d_in[4];
    const float* b0        = (const float*)d_in[5];
    const float* Wn1       = (const float*)d_in[6];
    const float* bn1       = (const float*)d_in[7];
    const float* Wn2       = (const float*)d_in[8];
    const float* bn2       = (const float*)d_in[9];
    const float* root      = (const float*)d_in[10];
    const float* conv_bias = (const float*)d_in[11];
    const float* lstm_Wih  = (const float*)d_in[12];
    const float* lstm_Whh  = (const float*)d_in[13];
    const float* lstm_b    = (const float*)d_in[14];
    const float* Wo1       = (const float*)d_in[15];
    const float* bo1       = (const float*)d_in[16];
    const float* Wo2       = (const float*)d_in[17];
    const float* bo2       = (const float*)d_in[18];
    float* out = (float*)d_out;

    init_state_kernel<<<(NN * DD + 255) / 256, 256>>>();
    seg_kernel<<<(NN + 255) / 256, 256>>>(batch);
    h0_kernel<<<(NN * DD + 255) / 256, 256>>>(x, W0, b0);
    hid_kernel<<<EE, 128>>>(edge_attr, Wn1, bn1);

    dim3 ggrid(DSQ / 128, (EE + 127) / 128);           // 32 x 313
    ew_gemm_kernel<<<ggrid, 256>>>(Wn2, bn2);

    for (int l = 0; l < LL; ++l) {
        conv_msg_kernel<<<(EE + 3) / 4, 256>>>(edgeidx);
        h_update_kernel<<<(NN + 3) / 4, 256>>>(root + (size_t)l * DSQ, conv_bias + l * DD);
    }

    for (int m = 0; m < MM; ++m) {
        lstm_kernel<<<BB, 256>>>(lstm_Wih, lstm_Whh, lstm_b);
        escore_kernel<<<(NN + 7) / 8, 256>>>(batch);
        pool_kernel<<<BB, 64>>>();
    }

    out_kernel<<<BB, 64>>>(Wo1, bo1, Wo2, bo2, out);
}

// round 9
// speedup vs baseline: 1.4471x; 1.4471x over previous
#include <cuda_runtime.h>
#include <cuda_bf16.h>
#include <cuda_fp16.h>
#include <cstdint>
#include <cstddef>

// Problem constants
#define NN 10000
#define EE 40000
#define DIN 11
#define DD 64
#define FEA 4
#define LL 4
#define BB 512
#define MM 3
#define DH 128          // 2*D, edge-MLP hidden
#define DSQ 4096        // D*D

// ---------------- device scratch (static globals; no allocation) ----------------
__device__ __half g_EWh[(size_t)EE * DSQ];   // 327 MB: per-edge weight matrices (fp16)
__device__ float g_hid[(size_t)EE * DH];     // 20 MB: silu(ea@Wn1+bn1)
__device__ float g_h[NN * DD];               // node features
__device__ float g_aggr[NN * DD];            // scatter accumulator
__device__ float g_escore[NN];               // attention logits
__device__ float g_qstar[BB * 2 * DD];
__device__ float g_hs[BB * DD];
__device__ float g_cs[BB * DD];
__device__ int   g_segstart[BB + 1];

__device__ __forceinline__ float sigf(float x) { return 1.f / (1.f + expf(-x)); }

// ---------------- tf32 helpers ----------------
__device__ __forceinline__ uint32_t f2tf32(float v) {
    uint32_t r;
    asm("cvt.rna.tf32.f32 %0, %1;" : "=r"(r) : "f"(v));
    return r;
}
__device__ __forceinline__ void split_tf32(float v, uint32_t& hi, uint32_t& lo) {
    hi = f2tf32(v);
    lo = f2tf32(v - __uint_as_float(hi));
}
__device__ __forceinline__ void mma_tf32(float* c, const uint32_t* a, uint32_t b0, uint32_t b1) {
    asm volatile(
        "mma.sync.aligned.m16n8k8.row.col.f32.tf32.tf32.f32 "
        "{%0,%1,%2,%3}, {%4,%5,%6,%7}, {%8,%9}, {%0,%1,%2,%3};"
        : "+f"(c[0]), "+f"(c[1]), "+f"(c[2]), "+f"(c[3])
        : "r"(a[0]), "r"(a[1]), "r"(a[2]), "r"(a[3]), "r"(b0), "r"(b1));
}

// ---------------- init: zero state ----------------
__global__ void init_state_kernel() {
    int i = blockIdx.x * 256 + threadIdx.x;
    if (i < NN * DD) g_aggr[i] = 0.f;
    if (i < BB * 2 * DD) g_qstar[i] = 0.f;
    if (i < BB * DD) { g_hs[i] = 0.f; g_cs[i] = 0.f; }
}

// ---------------- segment starts from sorted batch ----------------
__global__ void seg_kernel(const int* __restrict__ batch) {
    int i = blockIdx.x * 256 + threadIdx.x;
    if (i >= NN) return;
    int bcur = batch[i];
    int bprev = (i == 0) ? -1 : batch[i - 1];
    for (int g = bprev + 1; g <= bcur; ++g) g_segstart[g] = i;
    if (i == NN - 1)
        for (int g = bcur + 1; g <= BB; ++g) g_segstart[g] = NN;
}

// ---------------- h0 = x @ W0 + b0 ----------------
__global__ void h0_kernel(const float* __restrict__ x, const float* __restrict__ W0,
                          const float* __restrict__ b0) {
    int idx = blockIdx.x * 256 + threadIdx.x;
    if (idx >= NN * DD) return;
    int n = idx >> 6, f = idx & 63;
    float acc = b0[f];
#pragma unroll
    for (int d = 0; d < DIN; ++d) acc += x[n * DIN + d] * W0[d * DD + f];
    g_h[idx] = acc;
}

// ---------------- hid = silu(edge_attr @ Wn1 + bn1) ----------------
__global__ void hid_kernel(const float* __restrict__ ea, const float* __restrict__ Wn1,
                           const float* __restrict__ bn1) {
    int idx = blockIdx.x * 256 + threadIdx.x;
    if (idx >= EE * DH) return;
    int e = idx >> 7, k = idx & 127;
    float4 a = *(const float4*)&ea[e * 4];
    float v = bn1[k] + a.x * Wn1[k] + a.y * Wn1[DH + k] + a.z * Wn1[2 * DH + k]
            + a.w * Wn1[3 * DH + k];
    g_hid[(size_t)e * DH + k] = v * sigf(v);
}

// ================= EW GEMM via mma.sync tf32 (3-term split), fp16 output =================
// C[E,4096] = hid[E,128] @ Wn2[128,4096] + bn2.
// CTA tile 128x128, K chunks of 64. 8 warps: 4 along M (32 rows), 2 along N (64 cols).
// Smem strides padded for conflict-free m16n8k8 fragment lds: A stride 68, B stride 136.
#define SA 68
#define SB 136
#define EW_SMEM_FLOATS (128 * SA + 64 * SB + 128)
#define EW_SMEM_BYTES (EW_SMEM_FLOATS * 4)

__global__ void __launch_bounds__(256, 2) ew_gemm_mma(const float* __restrict__ Wn2,
                                                      const float* __restrict__ bn2) {
    extern __shared__ float smem[];
    float* As = smem;                    // [128][SA]
    float* Bs = smem + 128 * SA;         // [64][SB]
    float* bias = smem + 128 * SA + 64 * SB;  // [128]

    const int tid = threadIdx.x;
    const int wid = tid >> 5, lane = tid & 31;
    const int g = lane >> 2, tig = lane & 3;
    const int wm = wid & 3, wn = wid >> 2;          // warp position: 4 x 2
    const int n0 = blockIdx.x * 128;
    const int m0 = blockIdx.y * 128;

    if (tid < 128) bias[tid] = bn2[n0 + tid];

    float C[2][8][4];
#pragma unroll
    for (int mt = 0; mt < 2; ++mt)
#pragma unroll
        for (int nt = 0; nt < 8; ++nt)
#pragma unroll
            for (int r = 0; r < 4; ++r) C[mt][nt][r] = 0.f;

#pragma unroll
    for (int kc = 0; kc < 2; ++kc) {
        // ---- load A chunk: hid[m0..+127][kc*64..+63] ----
#pragma unroll
        for (int i = 0; i < 8; ++i) {
            int idx = tid + i * 256;               // 2048 float4
            int row = idx >> 4, f4 = idx & 15;
            float4 v = make_float4(0.f, 0.f, 0.f, 0.f);
            if (m0 + row < EE)
                v = *(const float4*)&g_hid[(size_t)(m0 + row) * DH + kc * 64 + f4 * 4];
            *(float4*)&As[row * SA + f4 * 4] = v;
        }
        // ---- load B chunk: Wn2[kc*64..+63][n0..+127] ----
#pragma unroll
        for (int i = 0; i < 8; ++i) {
            int idx = tid + i * 256;               // 2048 float4
            int row = idx >> 5, f4 = idx & 31;
            float4 v = *(const float4*)&Wn2[(size_t)(kc * 64 + row) * DSQ + n0 + f4 * 4];
            *(float4*)&Bs[row * SB + f4 * 4] = v;
        }
        __syncthreads();

#pragma unroll
        for (int k8 = 0; k8 < 8; ++k8) {
            int k0 = k8 * 8;
            // A fragments (2 m-tiles), hi/lo
            uint32_t ah[2][4], al[2][4];
#pragma unroll
            for (int mt = 0; mt < 2; ++mt) {
                int rb = wm * 32 + mt * 16;
                float f0 = As[(rb + g) * SA + k0 + tig];
                float f1 = As[(rb + g + 8) * SA + k0 + tig];
                float f2 = As[(rb + g) * SA + k0 + tig + 4];
                float f3 = As[(rb + g + 8) * SA + k0 + tig + 4];
                split_tf32(f0, ah[mt][0], al[mt][0]);
                split_tf32(f1, ah[mt][1], al[mt][1]);
                split_tf32(f2, ah[mt][2], al[mt][2]);
                split_tf32(f3, ah[mt][3], al[mt][3]);
            }
#pragma unroll
            for (int nt = 0; nt < 8; ++nt) {
                int cb = wn * 64 + nt * 8;
                float b0f = Bs[(k0 + tig) * SB + cb + g];
                float b1f = Bs[(k0 + tig + 4) * SB + cb + g];
                uint32_t bh0, bl0, bh1, bl1;
                split_tf32(b0f, bh0, bl0);
                split_tf32(b1f, bh1, bl1);
#pragma unroll
                for (int mt = 0; mt < 2; ++mt) {
                    mma_tf32(C[mt][nt], ah[mt], bh0, bh1);   // hi*hi
                    mma_tf32(C[mt][nt], ah[mt], bl0, bl1);   // hi*lo
                    mma_tf32(C[mt][nt], al[mt], bh0, bh1);   // lo*hi
                }
            }
        }
        __syncthreads();
    }

    // ---- epilogue: bias add, fp16 store ----
#pragma unroll
    for (int mt = 0; mt < 2; ++mt) {
        int r0 = m0 + wm * 32 + mt * 16 + g;
        int r1 = r0 + 8;
#pragma unroll
        for (int nt = 0; nt < 8; ++nt) {
            int c = wn * 64 + nt * 8 + tig * 2;    // local col, even
            float bz0 = bias[c], bz1 = bias[c + 1];
            if (r0 < EE)
                *(__half2*)(g_EWh + (size_t)r0 * DSQ + n0 + c) =
                    __floats2half2_rn(C[mt][nt][0] + bz0, C[mt][nt][1] + bz1);
            if (r1 < EE)
                *(__half2*)(g_EWh + (size_t)r1 * DSQ + n0 + c) =
                    __floats2half2_rn(C[mt][nt][2] + bz0, C[mt][nt][3] + bz1);
        }
    }
}

// ---------------- per-layer: msg = h[src] @ EW[e] (fp16), scatter-add into aggr ---------
__global__ void conv_msg_kernel(const int* __restrict__ ei) {
    __shared__ float sh[8][64];
    int sub = threadIdx.x >> 5;                        // 8 edges / block, 1 warp each
    int t = threadIdx.x & 31;
    int e = blockIdx.x * 8 + sub;
    if (e >= EE) return;
    int src = ei[e];
    int dst = ei[EE + e];
    sh[sub][t] = g_h[src * DD + t];
    sh[sub][32 + t] = g_h[src * DD + 32 + t];
    __syncwarp();
    const __half2* ew2 = (const __half2*)(g_EWh + (size_t)e * DSQ) + t;
    float a0 = 0.f, a1 = 0.f;
#pragma unroll
    for (int d = 0; d < 64; ++d) {
        float2 w = __half22float2(ew2[d * 32]);
        float hv = sh[sub][d];
        a0 += hv * w.x;
        a1 += hv * w.y;
    }
    atomicAdd(&g_aggr[dst * DD + 2 * t], a0);
    atomicAdd(&g_aggr[dst * DD + 2 * t + 1], a1);
}

// ---------------- per-layer: h += aggr + h@root[l] + bias[l]; re-zero aggr ----------------
__global__ void h_update_kernel(const float* __restrict__ root_l,
                                const float* __restrict__ bias_l) {
    __shared__ float sh[4][64];
    int sub = threadIdx.x >> 6;
    int f = threadIdx.x & 63;
    int n = blockIdx.x * 4 + sub;
    sh[sub][f] = g_h[n * DD + f];
    __syncthreads();
    float acc = 0.f;
#pragma unroll 16
    for (int d = 0; d < 64; ++d) acc += sh[sub][d] * root_l[d * DD + f];
    g_h[n * DD + f] = sh[sub][f] + g_aggr[n * DD + f] + acc + bias_l[f];
    g_aggr[n * DD + f] = 0.f;
}

// ---------------- Set2Set LSTM step ----------------
__global__ void lstm_kernel(const float* __restrict__ Wih, const float* __restrict__ Whh,
                            const float* __restrict__ bvec) {
    int b = blockIdx.x, t = threadIdx.x;
    int warp = t >> 5, lane = t & 31;
    __shared__ float sq[128], shh[64], gs[256];
    if (t < 128) sq[t] = g_qstar[b * 128 + t];
    if (t < 64) shh[t] = g_hs[b * 64 + t];
    __syncthreads();
    for (int g = warp; g < 256; g += 8) {
        float acc = 0.f;
#pragma unroll
        for (int k = 0; k < 4; ++k) acc += sq[lane + k * 32] * Wih[g * 128 + lane + k * 32];
#pragma unroll
        for (int k = 0; k < 2; ++k) acc += shh[lane + k * 32] * Whh[g * 64 + lane + k * 32];
#pragma unroll
        for (int o = 16; o > 0; o >>= 1) acc += __shfl_down_sync(0xffffffffu, acc, o);
        if (lane == 0) gs[g] = acc + bvec[g];
    }
    __syncthreads();
    if (t < 64) {
        float gi = gs[t], gf = gs[64 + t], gg = gs[128 + t], go = gs[192 + t];
        float c = sigf(gf) * g_cs[b * 64 + t] + sigf(gi) * tanhf(gg);
        float hv = sigf(go) * tanhf(c);
        g_cs[b * 64 + t] = c;
        g_hs[b * 64 + t] = hv;
    }
}

// ---------------- e[n] = h[n] . q[batch[n]] ----------------
__global__ void escore_kernel(const int* __restrict__ batch) {
    int warp = threadIdx.x >> 5, lane = threadIdx.x & 31;
    int n = blockIdx.x * 8 + warp;
    if (n >= NN) return;
    int b = batch[n];
    float acc = g_h[n * 64 + lane] * g_hs[b * 64 + lane] +
                g_h[n * 64 + 32 + lane] * g_hs[b * 64 + 32 + lane];
#pragma unroll
    for (int o = 16; o > 0; o >>= 1) acc += __shfl_down_sync(0xffffffffu, acc, o);
    if (lane == 0) g_escore[n] = acc;
}

// ---------------- per-graph softmax pooling; q_star = [q, r] ----------------
__global__ void pool_kernel() {
    int b = blockIdx.x, t = threadIdx.x;               // 64 threads
    int s = g_segstart[b], e = g_segstart[b + 1];
    __shared__ float red[64];
    float m = -3.4e38f;
    for (int n = s + t; n < e; n += 64) m = fmaxf(m, g_escore[n]);
    red[t] = m;
    __syncthreads();
    for (int o = 32; o > 0; o >>= 1) { if (t < o) red[t] = fmaxf(red[t], red[t + o]); __syncthreads(); }
    float mx = red[0];
    __syncthreads();
    float den = 0.f;
    for (int n = s + t; n < e; n += 64) den += expf(g_escore[n] - mx);
    red[t] = den;
    __syncthreads();
    for (int o = 32; o > 0; o >>= 1) { if (t < o) red[t] += red[t + o]; __syncthreads(); }
    float inv = (e > s) ? (1.f / red[0]) : 0.f;
    float rf = 0.f;
    for (int n = s; n < e; ++n) rf += expf(g_escore[n] - mx) * g_h[n * 64 + t];
    rf *= inv;
    g_qstar[b * 128 + t] = g_hs[b * 64 + t];
    g_qstar[b * 128 + 64 + t] = rf;
}

// ---------------- out = silu(q_star @ Wo1 + bo1) @ Wo2 + bo2 ----------------
__global__ void out_kernel(const float* __restrict__ Wo1, const float* __restrict__ bo1,
                           const float* __restrict__ Wo2, const float* __restrict__ bo2,
                           float* __restrict__ out) {
    int b = blockIdx.x, f = threadIdx.x;               // 64 threads
    __shared__ float sq[128];
    __shared__ float red[64];
    sq[f] = g_qstar[b * 128 + f];
    sq[64 + f] = g_qstar[b * 128 + 64 + f];
    __syncthreads();
    float acc = bo1[f];
#pragma unroll 16
    for (int k = 0; k < 128; ++k) acc += sq[k] * Wo1[k * 64 + f];
    float s = acc * sigf(acc);
    red[f] = s * Wo2[f];
    __syncthreads();
    for (int o = 32; o > 0; o >>= 1) { if (f < o) red[f] += red[f + o]; __syncthreads(); }
    if (f == 0) out[b] = red[0] + bo2[0];
}

// ---------------- launch ----------------
extern "C" void kernel_launch(void* const* d_in, const int* in_sizes, int n_in,
                              void* d_out, int out_size) {
    const float* x         = (const float*)d_in[0];
    const int*   edgeidx   = (const int*)d_in[1];
    const float* edge_attr = (const float*)d_in[2];
    const int*   batch     = (const int*)d_in[3];
    const float* W0        = (const float*)d_in[4];
    const float* b0        = (const float*)d_in[5];
    const float* Wn1       = (const float*)d_in[6];
    const float* bn1       = (const float*)d_in[7];
    const float* Wn2       = (const float*)d_in[8];
    const float* bn2       = (const float*)d_in[9];
    const float* root      = (const float*)d_in[10];
    const float* conv_bias = (const float*)d_in[11];
    const float* lstm_Wih  = (const float*)d_in[12];
    const float* lstm_Whh  = (const float*)d_in[13];
    const float* lstm_b    = (const float*)d_in[14];
    const float* Wo1       = (const float*)d_in[15];
    const float* bo1       = (const float*)d_in[16];
    const float* Wo2       = (const float*)d_in[17];
    const float* bo2       = (const float*)d_in[18];
    float* out = (float*)d_out;

    cudaFuncSetAttribute(ew_gemm_mma, cudaFuncAttributeMaxDynamicSharedMemorySize,
                         EW_SMEM_BYTES);

    init_state_kernel<<<(NN * DD + 255) / 256, 256>>>();
    seg_kernel<<<(NN + 255) / 256, 256>>>(batch);
    h0_kernel<<<(NN * DD + 255) / 256, 256>>>(x, W0, b0);
    hid_kernel<<<(EE * DH + 255) / 256, 256>>>(edge_attr, Wn1, bn1);

    dim3 ggrid(32, (EE + 127) / 128);                  // 32 n-blocks x 313 m-blocks
    ew_gemm_mma<<<ggrid, 256, EW_SMEM_BYTES>>>(Wn2, bn2);

    for (int l = 0; l < LL; ++l) {
        conv_msg_kernel<<<(EE + 7) / 8, 256>>>(edgeidx);
        h_update_kernel<<<(NN + 3) / 4, 256>>>(root + (size_t)l * DSQ, conv_bias + l * DD);
    }

    for (int m = 0; m < MM; ++m) {
        lstm_kernel<<<BB, 256>>>(lstm_Wih, lstm_Whh, lstm_b);
        escore_kernel<<<(NN + 7) / 8, 256>>>(batch);
        pool_kernel<<<BB, 64>>>();
    }

    out_kernel<<<BB, 64>>>(Wo1, bo1, Wo2, bo2, out);
}

// round 11
// speedup vs baseline: 2.0890x; 1.4436x over previous
#include <cuda_runtime.h>
#include <cuda_bf16.h>
#include <cuda_fp16.h>
#include <cstdint>
#include <cstddef>

// Problem constants
#define NN 10000
#define EE 40000
#define DIN 11
#define DD 64
#define FEA 4
#define LL 4
#define BB 512
#define MM 3
#define DH 128          // 2*D, edge-MLP hidden
#define DSQ 4096        // D*D
#define EPAD 128        // padded edge rows for GEMM tile overrun

// ---------------- device scratch (static globals; no allocation) ----------------
__device__ __half g_EWh[(size_t)EE * DSQ];          // 327 MB: per-edge weight matrices (fp16)
__device__ __half g_hidh[(size_t)(EE + EPAD) * DH]; // hid hi (fp16)
__device__ __half g_hidl[(size_t)(EE + EPAD) * DH]; // hid lo (fp16)
__device__ __half g_Wn2Th[(size_t)DSQ * DH];        // Wn2 transposed [n][k] hi
__device__ __half g_Wn2Tl[(size_t)DSQ * DH];        // Wn2 transposed [n][k] lo
__device__ float g_h[NN * DD];               // node features
__device__ float g_aggr[NN * DD];            // scatter accumulator
__device__ float g_escore[NN];               // attention logits
__device__ float g_qstar[BB * 2 * DD];
__device__ float g_hs[BB * DD];
__device__ float g_cs[BB * DD];
__device__ int   g_segstart[BB + 1];

__device__ __forceinline__ float sigf(float x) { return 1.f / (1.f + expf(-x)); }

__device__ __forceinline__ void mma_f16(float* c, const uint32_t* a, uint32_t b0, uint32_t b1) {
    asm volatile(
        "mma.sync.aligned.m16n8k16.row.col.f32.f16.f16.f32 "
        "{%0,%1,%2,%3}, {%4,%5,%6,%7}, {%8,%9}, {%0,%1,%2,%3};"
        : "+f"(c[0]), "+f"(c[1]), "+f"(c[2]), "+f"(c[3])
        : "r"(a[0]), "r"(a[1]), "r"(a[2]), "r"(a[3]), "r"(b0), "r"(b1));
}

// ---------------- init: zero state ----------------
__global__ void init_state_kernel() {
    int i = blockIdx.x * 256 + threadIdx.x;
    if (i < NN * DD) g_aggr[i] = 0.f;
    if (i < BB * 2 * DD) g_qstar[i] = 0.f;
    if (i < BB * DD) { g_hs[i] = 0.f; g_cs[i] = 0.f; }
    if (i < EPAD * DH) {                               // zero the A-tile overrun pad
        g_hidh[(size_t)EE * DH + i] = __float2half(0.f);
        g_hidl[(size_t)EE * DH + i] = __float2half(0.f);
    }
}

// ---------------- segment starts from sorted batch ----------------
__global__ void seg_kernel(const int* __restrict__ batch) {
    int i = blockIdx.x * 256 + threadIdx.x;
    if (i >= NN) return;
    int bcur = batch[i];
    int bprev = (i == 0) ? -1 : batch[i - 1];
    for (int g = bprev + 1; g <= bcur; ++g) g_segstart[g] = i;
    if (i == NN - 1)
        for (int g = bcur + 1; g <= BB; ++g) g_segstart[g] = NN;
}

// ---------------- h0 = x @ W0 + b0 ----------------
__global__ void h0_kernel(const float* __restrict__ x, const float* __restrict__ W0,
                          const float* __restrict__ b0) {
    int idx = blockIdx.x * 256 + threadIdx.x;
    if (idx >= NN * DD) return;
    int n = idx >> 6, f = idx & 63;
    float acc = b0[f];
#pragma unroll
    for (int d = 0; d < DIN; ++d) acc += x[n * DIN + d] * W0[d * DD + f];
    g_h[idx] = acc;
}

// ---------------- hid = silu(edge_attr @ Wn1 + bn1), stored as fp16 hi/lo ----------------
__global__ void hid_kernel(const float* __restrict__ ea, const float* __restrict__ Wn1,
                           const float* __restrict__ bn1) {
    int idx = blockIdx.x * 256 + threadIdx.x;
    if (idx >= EE * DH) return;
    int e = idx >> 7, k = idx & 127;
    float4 a = *(const float4*)&ea[e * 4];
    float v = bn1[k] + a.x * Wn1[k] + a.y * Wn1[DH + k] + a.z * Wn1[2 * DH + k]
            + a.w * Wn1[3 * DH + k];
    v = v * sigf(v);
    __half hh = __float2half_rn(v);
    __half hl = __float2half_rn(v - __half2float(hh));
    g_hidh[idx] = hh;
    g_hidl[idx] = hl;
}

// ---------------- transpose+split Wn2 -> [n][k] fp16 hi/lo ----------------
__global__ void wn2t_kernel(const float* __restrict__ Wn2) {
    int idx = blockIdx.x * 256 + threadIdx.x;          // DSQ*DH
    if (idx >= DSQ * DH) return;
    int n = idx >> 7, k = idx & 127;
    float v = Wn2[(size_t)k * DSQ + n];
    __half hh = __float2half_rn(v);
    __half hl = __float2half_rn(v - __half2float(hh));
    g_Wn2Th[idx] = hh;
    g_Wn2Tl[idx] = hl;
}

// ================= EW GEMM via mma.sync m16n8k16 fp16 (3-term split), fp16 output =========
// C[E,4096] = hid[E,128] @ Wn2[128,4096] + bn2.
// CTA tile 128x128, K in 2 chunks of 64. 8 warps: 4 along M (32 rows), 2 along N (64 cols).
// Smem word stride 36 per row (32 data + 4 pad) -> all fragment lds conflict-free.
#define SAW 36
#define SM_AH 0
#define SM_AL (128 * SAW)
#define SM_BH (2 * 128 * SAW)
#define SM_BL (3 * 128 * SAW)
#define SM_BIAS (4 * 128 * SAW)
#define EW_SMEM_WORDS (4 * 128 * SAW + 128)
#define EW_SMEM_BYTES (EW_SMEM_WORDS * 4)

__global__ void __launch_bounds__(256, 2) ew_gemm_mma(const float* __restrict__ bn2) {
    extern __shared__ uint32_t smw[];
    const int tid = threadIdx.x;
    const int wid = tid >> 5, lane = tid & 31;
    const int g = lane >> 2, tig = lane & 3;
    const int wm = wid & 3, wn = wid >> 2;             // warp position: 4 x 2
    const int n0 = blockIdx.x * 128;
    const int m0 = blockIdx.y * 128;

    if (tid < 128) ((float*)(smw + SM_BIAS))[tid] = bn2[n0 + tid];

    float C[2][8][4];
#pragma unroll
    for (int mt = 0; mt < 2; ++mt)
#pragma unroll
        for (int nt = 0; nt < 8; ++nt)
#pragma unroll
            for (int r = 0; r < 4; ++r) C[mt][nt][r] = 0.f;

#pragma unroll
    for (int kc = 0; kc < 2; ++kc) {
        // ---- fill A hi/lo: 128 rows x 32 words (64 k-values) ----
#pragma unroll
        for (int i = 0; i < 4; ++i) {
            int idx = tid + i * 256;                   // 1024 uint4 slots
            int row = idx >> 3, q = idx & 7;           // 8 uint4 per row
            size_t goff = (size_t)(m0 + row) * DH + kc * 64 + q * 8;
            uint4 vh = *(const uint4*)(g_hidh + goff);
            uint4 vl = *(const uint4*)(g_hidl + goff);
            *(uint4*)(smw + SM_AH + row * SAW + q * 4) = vh;
            *(uint4*)(smw + SM_AL + row * SAW + q * 4) = vl;
        }
        // ---- fill B hi/lo: 128 n-rows x 32 words ----
#pragma unroll
        for (int i = 0; i < 4; ++i) {
            int idx = tid + i * 256;
            int row = idx >> 3, q = idx & 7;
            size_t goff = (size_t)(n0 + row) * DH + kc * 64 + q * 8;
            uint4 vh = *(const uint4*)(g_Wn2Th + goff);
            uint4 vl = *(const uint4*)(g_Wn2Tl + goff);
            *(uint4*)(smw + SM_BH + row * SAW + q * 4) = vh;
            *(uint4*)(smw + SM_BL + row * SAW + q * 4) = vl;
        }
        __syncthreads();

#pragma unroll
        for (int k16 = 0; k16 < 4; ++k16) {
            int kw = k16 * 8;
            uint32_t ah[2][4], al[2][4];
#pragma unroll
            for (int mt = 0; mt < 2; ++mt) {
                int r0 = (wm * 32 + mt * 16 + g) * SAW + kw;
                int r1 = (wm * 32 + mt * 16 + g + 8) * SAW + kw;
                ah[mt][0] = smw[SM_AH + r0 + tig];
                ah[mt][1] = smw[SM_AH + r1 + tig];
                ah[mt][2] = smw[SM_AH + r0 + 4 + tig];
                ah[mt][3] = smw[SM_AH + r1 + 4 + tig];
                al[mt][0] = smw[SM_AL + r0 + tig];
                al[mt][1] = smw[SM_AL + r1 + tig];
                al[mt][2] = smw[SM_AL + r0 + 4 + tig];
                al[mt][3] = smw[SM_AL + r1 + 4 + tig];
            }
#pragma unroll
            for (int nt = 0; nt < 8; ++nt) {
                int nrow = (wn * 64 + nt * 8 + g) * SAW + kw;
                uint32_t bh0 = smw[SM_BH + nrow + tig];
                uint32_t bh1 = smw[SM_BH + nrow + 4 + tig];
                uint32_t bl0 = smw[SM_BL + nrow + tig];
                uint32_t bl1 = smw[SM_BL + nrow + 4 + tig];
#pragma unroll
                for (int mt = 0; mt < 2; ++mt) {
                    mma_f16(C[mt][nt], ah[mt], bh0, bh1);   // hi*hi
                    mma_f16(C[mt][nt], ah[mt], bl0, bl1);   // hi*lo
                    mma_f16(C[mt][nt], al[mt], bh0, bh1);   // lo*hi
                }
            }
        }
        __syncthreads();
    }

    // ---- epilogue: bias add, fp16 store ----
    const float* bias = (const float*)(smw + SM_BIAS);
#pragma unroll
    for (int mt = 0; mt < 2; ++mt) {
        int r0 = m0 + wm * 32 + mt * 16 + g;
        int r1 = r0 + 8;
#pragma unroll
        for (int nt = 0; nt < 8; ++nt) {
            int c = wn * 64 + nt * 8 + tig * 2;        // local col, even
            float bz0 = bias[c], bz1 = bias[c + 1];
            if (r0 < EE)
                *(__half2*)(g_EWh + (size_t)r0 * DSQ + n0 + c) =
                    __floats2half2_rn(C[mt][nt][0] + bz0, C[mt][nt][1] + bz1);
            if (r1 < EE)
                *(__half2*)(g_EWh + (size_t)r1 * DSQ + n0 + c) =
                    __floats2half2_rn(C[mt][nt][2] + bz0, C[mt][nt][3] + bz1);
        }
    }
}

// ---------------- per-layer: msg = h[src] @ EW[e] (fp16), scatter-add into aggr ---------
__global__ void conv_msg_kernel(const int* __restrict__ ei) {
    __shared__ float sh[8][64];
    int sub = threadIdx.x >> 5;                        // 8 edges / block, 1 warp each
    int t = threadIdx.x & 31;
    int e = blockIdx.x * 8 + sub;
    if (e >= EE) return;
    int src = ei[e];
    int dst = ei[EE + e];
    sh[sub][t] = g_h[src * DD + t];
    sh[sub][32 + t] = g_h[src * DD + 32 + t];
    __syncwarp();
    const __half2* ew2 = (const __half2*)(g_EWh + (size_t)e * DSQ) + t;
    float a0 = 0.f, a1 = 0.f;
#pragma unroll
    for (int d = 0; d < 64; ++d) {
        float2 w = __half22float2(ew2[d * 32]);
        float hv = sh[sub][d];
        a0 += hv * w.x;
        a1 += hv * w.y;
    }
    atomicAdd(&g_aggr[dst * DD + 2 * t], a0);
    atomicAdd(&g_aggr[dst * DD + 2 * t + 1], a1);
}

// ---------------- per-layer: h += aggr + h@root[l] + bias[l]; re-zero aggr ----------------
__global__ void h_update_kernel(const float* __restrict__ root_l,
                                const float* __restrict__ bias_l) {
    __shared__ float sh[4][64];
    int sub = threadIdx.x >> 6;
    int f = threadIdx.x & 63;
    int n = blockIdx.x * 4 + sub;
    sh[sub][f] = g_h[n * DD + f];
    __syncthreads();
    float acc = 0.f;
#pragma unroll 16
    for (int d = 0; d < 64; ++d) acc += sh[sub][d] * root_l[d * DD + f];
    g_h[n * DD + f] = sh[sub][f] + g_aggr[n * DD + f] + acc + bias_l[f];
    g_aggr[n * DD + f] = 0.f;
}

// ---------------- Set2Set LSTM step ----------------
__global__ void lstm_kernel(const float* __restrict__ Wih, const float* __restrict__ Whh,
                            const float* __restrict__ bvec) {
    int b = blockIdx.x, t = threadIdx.x;
    int warp = t >> 5, lane = t & 31;
    __shared__ float sq[128], shh[64], gs[256];
    if (t < 128) sq[t] = g_qstar[b * 128 + t];
    if (t < 64) shh[t] = g_hs[b * 64 + t];
    __syncthreads();
    for (int g = warp; g < 256; g += 8) {
        float acc = 0.f;
#pragma unroll
        for (int k = 0; k < 4; ++k) acc += sq[lane + k * 32] * Wih[g * 128 + lane + k * 32];
#pragma unroll
        for (int k = 0; k < 2; ++k) acc += shh[lane + k * 32] * Whh[g * 64 + lane + k * 32];
#pragma unroll
        for (int o = 16; o > 0; o >>= 1) acc += __shfl_down_sync(0xffffffffu, acc, o);
        if (lane == 0) gs[g] = acc + bvec[g];
    }
    __syncthreads();
    if (t < 64) {
        float gi = gs[t], gf = gs[64 + t], gg = gs[128 + t], go = gs[192 + t];
        float c = sigf(gf) * g_cs[b * 64 + t] + sigf(gi) * tanhf(gg);
        float hv = sigf(go) * tanhf(c);
        g_cs[b * 64 + t] = c;
        g_hs[b * 64 + t] = hv;
    }
}

// ---------------- e[n] = h[n] . q[batch[n]] ----------------
__global__ void escore_kernel(const int* __restrict__ batch) {
    int warp = threadIdx.x >> 5, lane = threadIdx.x & 31;
    int n = blockIdx.x * 8 + warp;
    if (n >= NN) return;
    int b = batch[n];
    float acc = g_h[n * 64 + lane] * g_hs[b * 64 + lane] +
                g_h[n * 64 + 32 + lane] * g_hs[b * 64 + 32 + lane];
#pragma unroll
    for (int o = 16; o > 0; o >>= 1) acc += __shfl_down_sync(0xffffffffu, acc, o);
    if (lane == 0) g_escore[n] = acc;
}

// ---------------- per-graph softmax pooling; q_star = [q, r] ----------------
__global__ void pool_kernel() {
    int b = blockIdx.x, t = threadIdx.x;               // 64 threads
    int s = g_segstart[b], e = g_segstart[b + 1];
    __shared__ float red[64];
    float m = -3.4e38f;
    for (int n = s + t; n < e; n += 64) m = fmaxf(m, g_escore[n]);
    red[t] = m;
    __syncthreads();
    for (int o = 32; o > 0; o >>= 1) { if (t < o) red[t] = fmaxf(red[t], red[t + o]); __syncthreads(); }
    float mx = red[0];
    __syncthreads();
    float den = 0.f;
    for (int n = s + t; n < e; n += 64) den += expf(g_escore[n] - mx);
    red[t] = den;
    __syncthreads();
    for (int o = 32; o > 0; o >>= 1) { if (t < o) red[t] += red[t + o]; __syncthreads(); }
    float inv = (e > s) ? (1.f / red[0]) : 0.f;
    float rf = 0.f;
    for (int n = s; n < e; ++n) rf += expf(g_escore[n] - mx) * g_h[n * 64 + t];
    rf *= inv;
    g_qstar[b * 128 + t] = g_hs[b * 64 + t];
    g_qstar[b * 128 + 64 + t] = rf;
}

// ---------------- out = silu(q_star @ Wo1 + bo1) @ Wo2 + bo2 ----------------
__global__ void out_kernel(const float* __restrict__ Wo1, const float* __restrict__ bo1,
                           const float* __restrict__ Wo2, const float* __restrict__ bo2,
                           float* __restrict__ out) {
    int b = blockIdx.x, f = threadIdx.x;               // 64 threads
    __shared__ float sq[128];
    __shared__ float red[64];
    sq[f] = g_qstar[b * 128 + f];
    sq[64 + f] = g_qstar[b * 128 + 64 + f];
    __syncthreads();
    float acc = bo1[f];
#pragma unroll 16
    for (int k = 0; k < 128; ++k) acc += sq[k] * Wo1[k * 64 + f];
    float s = acc * sigf(acc);
    red[f] = s * Wo2[f];
    __syncthreads();
    for (int o = 32; o > 0; o >>= 1) { if (f < o) red[f] += red[f + o]; __syncthreads(); }
    if (f == 0) out[b] = red[0] + bo2[0];
}

// ---------------- launch ----------------
extern "C" void kernel_launch(void* const* d_in, const int* in_sizes, int n_in,
                              void* d_out, int out_size) {
    const float* x         = (const float*)d_in[0];
    const int*   edgeidx   = (const int*)d_in[1];
    const float* edge_attr = (const float*)d_in[2];
    const int*   batch     = (const int*)d_in[3];
    const float* W0        = (const float*)d_in[4];
    const float* b0        = (const float*)d_in[5];
    const float* Wn1       = (const float*)d_in[6];
    const float* bn1       = (const float*)d_in[7];
    const float* Wn2       = (const float*)d_in[8];
    const float* bn2       = (const float*)d_in[9];
    const float* root      = (const float*)d_in[10];
    const float* conv_bias = (const float*)d_in[11];
    const float* lstm_Wih  = (const float*)d_in[12];
    const float* lstm_Whh  = (const float*)d_in[13];
    const float* lstm_b    = (const float*)d_in[14];
    const float* Wo1       = (const float*)d_in[15];
    const float* bo1       = (const float*)d_in[16];
    const float* Wo2       = (const float*)d_in[17];
    const float* bo2       = (const float*)d_in[18];
    float* out = (float*)d_out;

    cudaFuncSetAttribute(ew_gemm_mma, cudaFuncAttributeMaxDynamicSharedMemorySize,
                         EW_SMEM_BYTES);

    init_state_kernel<<<(NN * DD + 255) / 256, 256>>>();
    seg_kernel<<<(NN + 255) / 256, 256>>>(batch);
    h0_kernel<<<(NN * DD + 255) / 256, 256>>>(x, W0, b0);
    hid_kernel<<<(EE * DH + 255) / 256, 256>>>(edge_attr, Wn1, bn1);
    wn2t_kernel<<<(DSQ * DH + 255) / 256, 256>>>(Wn2);

    dim3 ggrid(32, (EE + 127) / 128);                  // 32 n-blocks x 313 m-blocks
    ew_gemm_mma<<<ggrid, 256, EW_SMEM_BYTES>>>(bn2);

    for (int l = 0; l < LL; ++l) {
        conv_msg_kernel<<<(EE + 7) / 8, 256>>>(edgeidx);
        h_update_kernel<<<(NN + 3) / 4, 256>>>(root + (size_t)l * DSQ, conv_bias + l * DD);
    }

    for (int m = 0; m < MM; ++m) {
        lstm_kernel<<<BB, 256>>>(lstm_Wih, lstm_Whh, lstm_b);
        escore_kernel<<<(NN + 7) / 8, 256>>>(batch);
        pool_kernel<<<BB, 64>>>();
    }

    out_kernel<<<BB, 64>>>(Wo1, bo1, Wo2, bo2, out);
}